// round 1
// baseline (speedup 1.0000x reference)
#include <cuda_runtime.h>
#include <cstdint>
#include <cstddef>

// ---------------- problem constants (static per setup_inputs) ----------------
constexpr int LQ    = 13294;          // sum of H*W over levels
constexpr int MROWS = 2 * LQ;         // batch-flattened rows = 26588
constexpr int KDIM  = 256;            // d_model

__constant__ int c_WH[4] = {100, 50, 25, 13};           // W == H per level
__constant__ int c_ST[4] = {0, 10000, 12500, 13125};    // level start index

// ---------------- scratch (device globals: allocation-free) ----------------
__device__ float g_value [MROWS * 256];   // value projection  [N*S, 8*32]
__device__ float g_off   [MROWS * 256];   // sampling offsets  [N*Lq, 256]
__device__ float g_logits[MROWS * 128];   // attention logits  [N*Lq, 128]
__device__ float g_samp  [MROWS * 256];   // attention output  [N*Lq, 256]

// ---------------- fp32 tiled GEMM: C[M,N] = A[M,256] @ B[256,N] + bias ------
// BM=128, BN=128, BK=16, 256 threads, 8x8 register tile per thread.
__global__ __launch_bounds__(256) void gemm_bias_k256(
    const float* __restrict__ A, const float* __restrict__ B,
    const float* __restrict__ bias, float* __restrict__ C,
    int M, int N)
{
    constexpr int BM = 128, BN = 128, BK = 16;
    __shared__ float As[BK][BM + 4];   // [k][m], +4 keeps float4 alignment
    __shared__ float Bs[BK][BN];       // [k][n]

    const int tid = threadIdx.x;
    const int m0 = blockIdx.x * BM;
    const int n0 = blockIdx.y * BN;
    const int tx = tid & 15;           // 0..15 -> 8 cols each
    const int ty = tid >> 4;           // 0..15 -> 8 rows each

    float acc[8][8] = {};

    for (int k0 = 0; k0 < KDIM; k0 += BK) {
        // load A tile: 128 rows x 16 k = 512 float4, 2 per thread
        #pragma unroll
        for (int i = 0; i < 2; ++i) {
            int v  = tid + i * 256;
            int r  = v >> 2;               // 0..127
            int kk = (v & 3) * 4;          // 0,4,8,12
            float4 av = make_float4(0.f, 0.f, 0.f, 0.f);
            int gm = m0 + r;
            if (gm < M)
                av = *(const float4*)(A + (size_t)gm * KDIM + k0 + kk);
            As[kk + 0][r] = av.x;
            As[kk + 1][r] = av.y;
            As[kk + 2][r] = av.z;
            As[kk + 3][r] = av.w;
        }
        // load B tile: 16 rows x 128 cols = 512 float4, 2 per thread
        #pragma unroll
        for (int i = 0; i < 2; ++i) {
            int v = tid + i * 256;
            int r = v >> 5;                // 0..15
            int c = (v & 31) * 4;          // 0..124
            *(float4*)&Bs[r][c] = *(const float4*)(B + (size_t)(k0 + r) * N + n0 + c);
        }
        __syncthreads();

        #pragma unroll
        for (int k = 0; k < BK; ++k) {
            float a[8], b[8];
            *(float4*)&a[0] = *(const float4*)&As[k][ty * 8];
            *(float4*)&a[4] = *(const float4*)&As[k][ty * 8 + 4];
            *(float4*)&b[0] = *(const float4*)&Bs[k][tx * 8];
            *(float4*)&b[4] = *(const float4*)&Bs[k][tx * 8 + 4];
            #pragma unroll
            for (int i = 0; i < 8; ++i)
                #pragma unroll
                for (int j = 0; j < 8; ++j)
                    acc[i][j] += a[i] * b[j];
        }
        __syncthreads();
    }

    #pragma unroll
    for (int i = 0; i < 8; ++i) {
        int gm = m0 + ty * 8 + i;
        if (gm >= M) break;
        #pragma unroll
        for (int j = 0; j < 8; j += 4) {
            int gn = n0 + tx * 8 + j;
            float4 o;
            o.x = acc[i][j + 0] + bias[gn + 0];
            o.y = acc[i][j + 1] + bias[gn + 1];
            o.z = acc[i][j + 2] + bias[gn + 2];
            o.w = acc[i][j + 3] + bias[gn + 3];
            *(float4*)(C + (size_t)gm * N + gn) = o;
        }
    }
}

// ---------------- deformable sampling + softmax ----------------
// grid = MROWS blocks (one per (n,lq)); 256 threads = 8 warps = 8 heads.
// Lane = head-dim channel (32). Per warp: softmax over 16 (level,point)
// logits, compute pixel coords, 16 samples x 4 corners bilinear gather-FMA.
__global__ __launch_bounds__(256) void sample_kernel(
    const float* __restrict__ refpts,   // [N,Lq,4,2]
    const float* __restrict__ value,    // [N,S,8,32]
    const float* __restrict__ offv,     // [N,Lq,256]
    const float* __restrict__ logits,   // [N,Lq,128]
    float* __restrict__ out)            // [N,Lq,256]
{
    const int q    = blockIdx.x;        // n*LQ + lq
    const int warp = threadIdx.x >> 5;  // head m
    const int lane = threadIdx.x & 31;
    const int n    = q / LQ;

    __shared__ float sh_w[8][16];
    __shared__ float sh_x[8][16];
    __shared__ float sh_y[8][16];

    // --- softmax over 16 logits (lanes 0..15 hold data; xor<=8 keeps halves) ---
    float l = (lane < 16) ? logits[(size_t)q * 128 + warp * 16 + lane] : -1e30f;
    float mx = l;
    #pragma unroll
    for (int o = 8; o > 0; o >>= 1) mx = fmaxf(mx, __shfl_xor_sync(0xffffffffu, mx, o));
    float e = __expf(l - mx);
    float sum = e;
    #pragma unroll
    for (int o = 8; o > 0; o >>= 1) sum += __shfl_xor_sync(0xffffffffu, sum, o);
    if (lane < 16) sh_w[warp][lane] = e / sum;

    // --- pixel coords: x = ref_x*W + off_x - 0.5 (division cancels) ---
    {
        int lvl = lane >> 3;            // level
        int c   = lane & 1;             // 0=x, 1=y
        int s   = lane >> 1;            // (level,point) index 0..15
        float offr = offv[(size_t)q * 256 + warp * 32 + lane];
        float ref  = refpts[((size_t)q * 4 + lvl) * 2 + c];
        float sz   = (float)c_WH[lvl];  // W == H for all levels
        float pix  = fmaf(ref, sz, offr) - 0.5f;
        if (c == 0) sh_x[warp][s] = pix; else sh_y[warp][s] = pix;
    }
    __syncwarp();

    const int WH[4] = {100, 50, 25, 13};
    const int ST[4] = {0, 10000, 12500, 13125};

    float acc = 0.f;
    const float* vbase = value + (size_t)n * LQ * 256 + warp * 32 + lane;

    #pragma unroll
    for (int s16 = 0; s16 < 16; ++s16) {
        const int lvl = s16 >> 2;
        const int Wl  = WH[lvl];        // compile-time (loop fully unrolled)
        const int st  = ST[lvl];
        float x  = sh_x[warp][s16];
        float y  = sh_y[warp][s16];
        float aw = sh_w[warp][s16];
        float x0f = floorf(x), y0f = floorf(y);
        int   x0 = (int)x0f, y0 = (int)y0f;
        float wx = x - x0f,  wy = y - y0f;

        #pragma unroll
        for (int dy = 0; dy < 2; ++dy) {
            int yi = y0 + dy;
            if (yi < 0 || yi >= Wl) continue;       // H == W
            float wyy = dy ? wy : (1.f - wy);
            #pragma unroll
            for (int dx = 0; dx < 2; ++dx) {
                int xi = x0 + dx;
                if (xi < 0 || xi >= Wl) continue;
                float wgt = aw * wyy * (dx ? wx : (1.f - wx));
                acc += wgt * __ldg(vbase + (size_t)(st + yi * Wl + xi) * 256);
            }
        }
    }
    out[(size_t)q * 256 + warp * 32 + lane] = acc;
}

// ---------------- launch ----------------
extern "C" void kernel_launch(void* const* d_in, const int* in_sizes, int n_in,
                              void* d_out, int out_size)
{
    const float* query  = (const float*)d_in[0];
    const float* refpts = (const float*)d_in[1];
    const float* flat   = (const float*)d_in[2];
    // d_in[3] spatial shapes, d_in[4] level starts: static, hardcoded
    const float* Wv     = (const float*)d_in[5];
    const float* bv     = (const float*)d_in[6];
    const float* Woff   = (const float*)d_in[7];
    const float* boff   = (const float*)d_in[8];
    const float* Wattn  = (const float*)d_in[9];
    const float* battn  = (const float*)d_in[10];
    const float* Wout   = (const float*)d_in[11];
    const float* bout   = (const float*)d_in[12];
    float* out = (float*)d_out;

    float *gv, *go, *gl, *gs;
    cudaGetSymbolAddress((void**)&gv, g_value);
    cudaGetSymbolAddress((void**)&go, g_off);
    cudaGetSymbolAddress((void**)&gl, g_logits);
    cudaGetSymbolAddress((void**)&gs, g_samp);

    const int mblk = (MROWS + 127) / 128;  // 208
    dim3 g256(mblk, 2), g128(mblk, 1);

    gemm_bias_k256<<<g256, 256>>>(flat,  Wv,    bv,    gv, MROWS, 256);
    gemm_bias_k256<<<g256, 256>>>(query, Woff,  boff,  go, MROWS, 256);
    gemm_bias_k256<<<g128, 256>>>(query, Wattn, battn, gl, MROWS, 128);
    sample_kernel <<<MROWS, 256>>>(refpts, gv, go, gl, gs);
    gemm_bias_k256<<<g256, 256>>>(gs,    Wout,  bout,  out, MROWS, 256);
}

// round 3
// speedup vs baseline: 2.1124x; 2.1124x over previous
#include <cuda_runtime.h>
#include <cuda_bf16.h>
#include <cstdint>
#include <cstddef>

// ---------------- problem constants ----------------
constexpr int LQ    = 13294;
constexpr int MROWS = 2 * LQ;          // 26588
constexpr int MPAD  = 208 * 128;       // 26624

__constant__ int c_WH[4] = {100, 50, 25, 13};

// ---------------- scratch (device globals, zero-initialized) ----------------
__device__ float g_value [MPAD * 256];
__device__ float g_off   [MPAD * 256];
__device__ float g_logits[MPAD * 128];
__device__ __nv_bfloat16 g_ahi[MPAD * 256];       // activation hi (pad rows stay 0)
__device__ __nv_bfloat16 g_alo[MPAD * 256];       // activation lo
__device__ __nv_bfloat16 g_wthi[4 * 256 * 256];   // transposed weights hi
__device__ __nv_bfloat16 g_wtlo[4 * 256 * 256];   // transposed weights lo

// ---------------- mma.sync helpers (baseline sm_80+ ISA: legal on compute_103) ----
__device__ __forceinline__ uint32_t smem_u32(const void* p) {
    uint32_t a;
    asm("{ .reg .u64 t; cvta.to.shared.u64 t, %1; cvt.u32.u64 %0, t; }" : "=r"(a) : "l"(p));
    return a;
}
__device__ __forceinline__ void ldsm_x4(uint32_t addr, uint32_t* r) {
    asm volatile("ldmatrix.sync.aligned.m8n8.x4.shared.b16 {%0,%1,%2,%3}, [%4];"
                 : "=r"(r[0]), "=r"(r[1]), "=r"(r[2]), "=r"(r[3]) : "r"(addr));
}
__device__ __forceinline__ void mma_bf16(float* c, const uint32_t* a, const uint32_t* b) {
    asm volatile("mma.sync.aligned.m16n8k16.row.col.f32.bf16.bf16.f32 "
                 "{%0,%1,%2,%3}, {%4,%5,%6,%7}, {%8,%9}, {%0,%1,%2,%3};"
                 : "+f"(c[0]), "+f"(c[1]), "+f"(c[2]), "+f"(c[3])
                 : "r"(a[0]), "r"(a[1]), "r"(a[2]), "r"(a[3]), "r"(b[0]), "r"(b[1]));
}

// ---------------- conversion kernels ----------------
__global__ __launch_bounds__(256) void conv_act(
    const float4* __restrict__ in, __nv_bfloat16* __restrict__ hi,
    __nv_bfloat16* __restrict__ lo, int n4)
{
    int i = blockIdx.x * 256 + threadIdx.x;
    if (i >= n4) return;
    float4 a = in[i];
    float v[4] = {a.x, a.y, a.z, a.w};
    __nv_bfloat16 h[4], l[4];
    #pragma unroll
    for (int j = 0; j < 4; ++j) {
        h[j] = __float2bfloat16(v[j]);
        l[j] = __float2bfloat16(v[j] - __bfloat162float(h[j]));
    }
    *(uint2*)(hi + (size_t)i * 4) = *(uint2*)h;
    *(uint2*)(lo + (size_t)i * 4) = *(uint2*)l;
}

// W [256, N] row-major -> Wt [N, 256] (K-contiguous) hi/lo
__global__ __launch_bounds__(256) void conv_wt(
    const float* __restrict__ W, __nv_bfloat16* __restrict__ hi,
    __nv_bfloat16* __restrict__ lo, int N)
{
    int idx = blockIdx.x * 256 + threadIdx.x;
    if (idx >= 256 * N) return;
    int k = idx / N, n = idx - k * N;
    float a = W[idx];
    __nv_bfloat16 h = __float2bfloat16(a);
    hi[n * 256 + k] = h;
    lo[n * 256 + k] = __float2bfloat16(a - __bfloat162float(h));
}

// ---------------- HMMA GEMM: C[M,N] = A[M,256] @ Wt^T + bias ----------------
// Split precision over effective K=768: parts: Ahi*Bhi, Ahi*Blo, Alo*Bhi.
// Tile 128x128, BK=32, 256 threads (8 warps, warp tile 32x64).
constexpr int BK   = 32;
constexpr int ROWE = 40;               // padded row stride in bf16 (80B, ldmatrix conflict-free)

__global__ __launch_bounds__(256) void gemm_mma(
    const __nv_bfloat16* __restrict__ Ahi, const __nv_bfloat16* __restrict__ Alo,
    const __nv_bfloat16* __restrict__ Bhi, const __nv_bfloat16* __restrict__ Blo,
    const float* __restrict__ bias, float* __restrict__ C, int M, int ldc)
{
    __shared__ __align__(16) __nv_bfloat16 As[2][128 * ROWE];
    __shared__ __align__(16) __nv_bfloat16 Bs[2][128 * ROWE];

    const int tid = threadIdx.x, wid = tid >> 5, lane = tid & 31;
    const int m0 = blockIdx.x * 128, n0 = blockIdx.y * 128;
    const int wm = (wid & 3) * 32, wn = (wid >> 2) * 64;

    // global-load coords: vector v = tid (+256): row = v>>2, 16B chunk = v&3
    const int rA = tid >> 2, cA = tid & 3;

    const uint32_t sA[2] = { smem_u32(&As[0][0]), smem_u32(&As[1][0]) };
    const uint32_t sB[2] = { smem_u32(&Bs[0][0]), smem_u32(&Bs[1][0]) };

    // ldmatrix lane addressing (byte offsets within tile)
    // A x4 (m16xk16, row-major): rows lane&15, col half (lane>>4)*8
    const uint32_t aRow = (lane & 15), aColB = (uint32_t)(lane >> 4) * 16;
    // B x4 (two n8 tiles): row = ((lane>>4)<<3) + (lane&7), col half ((lane>>3)&1)*8
    const uint32_t bRow = ((uint32_t)(lane >> 4) << 3) + (lane & 7);
    const uint32_t bColB = (uint32_t)((lane >> 3) & 1) * 16;

    float acc[2][8][4] = {};

    uint4 pA0, pA1, pB0, pB1;
    auto gload = [&](int kk) {
        const int part = kk >> 3, k0 = (kk & 7) * BK;
        const __nv_bfloat16* Ap = (part == 2) ? Alo : Ahi;
        const __nv_bfloat16* Bp = (part == 1) ? Blo : Bhi;
        pA0 = *(const uint4*)(Ap + (size_t)(m0 + rA)      * 256 + k0 + cA * 8);
        pA1 = *(const uint4*)(Ap + (size_t)(m0 + rA + 64) * 256 + k0 + cA * 8);
        pB0 = *(const uint4*)(Bp + (size_t)(n0 + rA)      * 256 + k0 + cA * 8);
        pB1 = *(const uint4*)(Bp + (size_t)(n0 + rA + 64) * 256 + k0 + cA * 8);
    };
    auto sstore = [&](int b) {
        *(uint4*)((char*)&As[b][0] + rA * 80 + cA * 16)        = pA0;
        *(uint4*)((char*)&As[b][0] + (rA + 64) * 80 + cA * 16) = pA1;
        *(uint4*)((char*)&Bs[b][0] + rA * 80 + cA * 16)        = pB0;
        *(uint4*)((char*)&Bs[b][0] + (rA + 64) * 80 + cA * 16) = pB1;
    };

    gload(0);
    sstore(0);
    __syncthreads();

    for (int kk = 0; kk < 24; ++kk) {
        const int b = kk & 1;
        if (kk < 23) gload(kk + 1);

        #pragma unroll
        for (int ks = 0; ks < 2; ++ks) {
            const uint32_t kB = ks * 32;   // 16 bf16 = 32 bytes
            uint32_t af[2][4], bf[4][4];
            #pragma unroll
            for (int mt = 0; mt < 2; ++mt)
                ldsm_x4(sA[b] + (wm + mt * 16 + aRow) * 80 + kB + aColB, af[mt]);
            #pragma unroll
            for (int p = 0; p < 4; ++p)
                ldsm_x4(sB[b] + (wn + p * 16 + bRow) * 80 + kB + bColB, bf[p]);
            #pragma unroll
            for (int mt = 0; mt < 2; ++mt)
                #pragma unroll
                for (int nt = 0; nt < 8; ++nt)
                    mma_bf16(acc[mt][nt], af[mt], &bf[nt >> 1][(nt & 1) * 2]);
        }

        if (kk < 23) { sstore((kk + 1) & 1); __syncthreads(); }
    }

    // epilogue: fragment (g=lane>>2, t=lane&3): c0,c1 -> (g, 2t); c2,c3 -> (g+8, 2t)
    const int g = lane >> 2, t2 = (lane & 3) * 2;
    #pragma unroll
    for (int mt = 0; mt < 2; ++mt) {
        const int r0 = m0 + wm + mt * 16 + g;
        #pragma unroll
        for (int nt = 0; nt < 8; ++nt) {
            const int c = n0 + wn + nt * 8 + t2;
            const float2 bsv = *(const float2*)(bias + c);
            if (r0 < M) {
                float2 o = { acc[mt][nt][0] + bsv.x, acc[mt][nt][1] + bsv.y };
                *(float2*)(C + (size_t)r0 * ldc + c) = o;
            }
            if (r0 + 8 < M) {
                float2 o = { acc[mt][nt][2] + bsv.x, acc[mt][nt][3] + bsv.y };
                *(float2*)(C + (size_t)(r0 + 8) * ldc + c) = o;
            }
        }
    }
}

// ---------------- deformable sampling: 4 queries/block, 4 heads/warp ----------------
// Emits bf16 hi/lo directly for the output GEMM.
__global__ __launch_bounds__(256) void sample_kernel(
    const float* __restrict__ refpts,   // [N*Lq, 4, 2]
    const float* __restrict__ value,    // [N*S, 256]
    const float* __restrict__ offv,     // [N*Lq, 256]
    const float* __restrict__ logits,   // [N*Lq, 128]
    __nv_bfloat16* __restrict__ ohi, __nv_bfloat16* __restrict__ olo)
{
    const int q0  = blockIdx.x * 4;
    const int tid = threadIdx.x;

    __shared__ float sh_w[4][8][17];
    __shared__ float sh_x[4][8][17];
    __shared__ float sh_y[4][8][17];

    // softmax weights: 32 runs of 16 logits, 16-lane segments
    #pragma unroll
    for (int i = 0; i < 2; ++i) {
        int run = i * 16 + (tid >> 4);
        int q = run >> 3, h = run & 7, l16 = tid & 15;
        float v = logits[(size_t)(q0 + q) * 128 + h * 16 + l16];
        float mx = v;
        #pragma unroll
        for (int o = 8; o > 0; o >>= 1) mx = fmaxf(mx, __shfl_xor_sync(0xffffffffu, mx, o));
        float e = __expf(v - mx);
        float s = e;
        #pragma unroll
        for (int o = 8; o > 0; o >>= 1) s += __shfl_xor_sync(0xffffffffu, s, o);
        sh_w[q][h][l16] = e / s;
    }

    // pixel coords: x = ref*W + off - 0.5
    #pragma unroll
    for (int q = 0; q < 4; ++q) {
        int h = tid >> 5, l32 = tid & 31;
        int lvl = l32 >> 3, cc = l32 & 1, s = l32 >> 1;
        float off = offv[(size_t)(q0 + q) * 256 + tid];
        float ref = refpts[((size_t)(q0 + q) * 4 + lvl) * 2 + cc];
        float pix = fmaf(ref, (float)c_WH[lvl], off) - 0.5f;
        if (cc == 0) sh_x[q][h][s] = pix; else sh_y[q][h][s] = pix;
    }
    __syncthreads();

    // gather: warp = (query, head-half); lane: 4 heads x 8 float4 channels
    const int w = tid >> 5, lane = tid & 31;
    const int q = w >> 1, half = w & 1;
    const int head = half * 4 + (lane >> 3);
    const int ci = lane & 7;
    const int qg = q0 + q;
    const int n  = (qg >= LQ) ? 1 : 0;

    const float4* v4 = (const float4*)value + (size_t)n * LQ * 64 + head * 8 + ci;
    float4 acc = make_float4(0.f, 0.f, 0.f, 0.f);

    const int WHl[4] = {100, 50, 25, 13};
    const int STl[4] = {0, 10000, 12500, 13125};

    #pragma unroll
    for (int s = 0; s < 16; ++s) {
        const int lvl = s >> 2;
        const int Wl = WHl[lvl], st = STl[lvl];
        float x = sh_x[q][head][s];
        float y = sh_y[q][head][s];
        float aw = sh_w[q][head][s];
        float xf = floorf(x), yf = floorf(y);
        int x0 = (int)xf, y0 = (int)yf;
        float wx = x - xf, wy = y - yf;
        #pragma unroll
        for (int dy = 0; dy < 2; ++dy) {
            int yi = y0 + dy;
            if (yi < 0 || yi >= Wl) continue;
            float wyy = dy ? wy : (1.f - wy);
            #pragma unroll
            for (int dx = 0; dx < 2; ++dx) {
                int xi = x0 + dx;
                if (xi < 0 || xi >= Wl) continue;
                float gw = aw * wyy * (dx ? wx : (1.f - wx));
                float4 v = __ldg(v4 + (st + yi * Wl + xi) * 64);
                acc.x = fmaf(gw, v.x, acc.x);
                acc.y = fmaf(gw, v.y, acc.y);
                acc.z = fmaf(gw, v.z, acc.z);
                acc.w = fmaf(gw, v.w, acc.w);
            }
        }
    }

    // emit bf16 hi/lo
    float av[4] = {acc.x, acc.y, acc.z, acc.w};
    __nv_bfloat16 h4[4], l4[4];
    #pragma unroll
    for (int j = 0; j < 4; ++j) {
        h4[j] = __float2bfloat16(av[j]);
        l4[j] = __float2bfloat16(av[j] - __bfloat162float(h4[j]));
    }
    const size_t eo = ((size_t)qg * 64 + head * 8 + ci) * 4;
    *(uint2*)(ohi + eo) = *(uint2*)h4;
    *(uint2*)(olo + eo) = *(uint2*)l4;
}

// ---------------- launch ----------------
extern "C" void kernel_launch(void* const* d_in, const int* in_sizes, int n_in,
                              void* d_out, int out_size)
{
    const float* query  = (const float*)d_in[0];
    const float* refpts = (const float*)d_in[1];
    const float* flat   = (const float*)d_in[2];
    const float* Wv     = (const float*)d_in[5];
    const float* bv     = (const float*)d_in[6];
    const float* Woff   = (const float*)d_in[7];
    const float* boff   = (const float*)d_in[8];
    const float* Wattn  = (const float*)d_in[9];
    const float* battn  = (const float*)d_in[10];
    const float* Wout   = (const float*)d_in[11];
    const float* bout   = (const float*)d_in[12];
    float* out = (float*)d_out;

    float *gv, *go, *gl;
    __nv_bfloat16 *ahi, *alo, *whi, *wlo;
    cudaGetSymbolAddress((void**)&gv,  g_value);
    cudaGetSymbolAddress((void**)&go,  g_off);
    cudaGetSymbolAddress((void**)&gl,  g_logits);
    cudaGetSymbolAddress((void**)&ahi, g_ahi);
    cudaGetSymbolAddress((void**)&alo, g_alo);
    cudaGetSymbolAddress((void**)&whi, g_wthi);
    cudaGetSymbolAddress((void**)&wlo, g_wtlo);

    const int WSLOT = 256 * 256;
    __nv_bfloat16 *wv_h = whi + 0 * WSLOT, *wv_l = wlo + 0 * WSLOT;
    __nv_bfloat16 *wo_h = whi + 1 * WSLOT, *wo_l = wlo + 1 * WSLOT;
    __nv_bfloat16 *wa_h = whi + 2 * WSLOT, *wa_l = wlo + 2 * WSLOT;
    __nv_bfloat16 *wu_h = whi + 3 * WSLOT, *wu_l = wlo + 3 * WSLOT;

    conv_wt<<<256, 256>>>(Wv,    wv_h, wv_l, 256);
    conv_wt<<<256, 256>>>(Woff,  wo_h, wo_l, 256);
    conv_wt<<<128, 256>>>(Wattn, wa_h, wa_l, 128);
    conv_wt<<<256, 256>>>(Wout,  wu_h, wu_l, 256);

    const int n4 = MROWS * 64;
    const int cblk = (n4 + 255) / 256;
    const int mblk = MPAD / 128;           // 208
    dim3 g256(mblk, 2), g128(mblk, 1);

    // value = flat @ Wv + bv
    conv_act<<<cblk, 256>>>((const float4*)flat, ahi, alo, n4);
    gemm_mma<<<g256, 256>>>(ahi, alo, wv_h, wv_l, bv, gv, MROWS, 256);

    // off = query @ Woff + boff ; logits = query @ Wattn + battn
    conv_act<<<cblk, 256>>>((const float4*)query, ahi, alo, n4);
    gemm_mma<<<g256, 256>>>(ahi, alo, wo_h, wo_l, boff,  go, MROWS, 256);
    gemm_mma<<<g128, 256>>>(ahi, alo, wa_h, wa_l, battn, gl, MROWS, 128);

    // sampling -> bf16 hi/lo activations for the output GEMM
    sample_kernel<<<MROWS / 4, 256>>>(refpts, gv, go, gl, ahi, alo);

    // out = samp @ Wout + bout
    gemm_mma<<<g256, 256>>>(ahi, alo, wu_h, wu_l, bout, out, MROWS, 256);
}

// round 4
// speedup vs baseline: 2.5304x; 1.1979x over previous
#include <cuda_runtime.h>
#include <cuda_bf16.h>
#include <cstdint>
#include <cstddef>

// ---------------- problem constants ----------------
constexpr int LQ    = 13294;
constexpr int MROWS = 2 * LQ;          // 26588
constexpr int MPAD  = 208 * 128;       // 26624

__constant__ int c_WH[4] = {100, 50, 25, 13};

// ---------------- scratch (device globals) ----------------
__device__ float g_value[MPAD * 256];
__device__ float g_qc   [MPAD * 384];             // [off(256) | logits(128)] per row
__device__ float g_samp [MPAD * 256];
__device__ float g_bqc  [384];                    // boff ++ battn
// transposed weights hi/lo: slot Wv [0,256), Wqc [256,640), Wout [640,896) rows of 256
__device__ __nv_bfloat16 g_wthi[896 * 256];
__device__ __nv_bfloat16 g_wtlo[896 * 256];

// ---------------- PTX helpers (all baseline sm_80+ ISA, legal on compute_103) ----
__device__ __forceinline__ uint32_t smem_u32(const void* p) {
    uint32_t a;
    asm("{ .reg .u64 t; cvta.to.shared.u64 t, %1; cvt.u32.u64 %0, t; }" : "=r"(a) : "l"(p));
    return a;
}
__device__ __forceinline__ void ldsm_x4(uint32_t addr, uint32_t* r) {
    asm volatile("ldmatrix.sync.aligned.m8n8.x4.shared.b16 {%0,%1,%2,%3}, [%4];"
                 : "=r"(r[0]), "=r"(r[1]), "=r"(r[2]), "=r"(r[3]) : "r"(addr));
}
__device__ __forceinline__ void mma_bf16(float* c, const uint32_t* a, const uint32_t* b) {
    asm volatile("mma.sync.aligned.m16n8k16.row.col.f32.bf16.bf16.f32 "
                 "{%0,%1,%2,%3}, {%4,%5,%6,%7}, {%8,%9}, {%0,%1,%2,%3};"
                 : "+f"(c[0]), "+f"(c[1]), "+f"(c[2]), "+f"(c[3])
                 : "r"(a[0]), "r"(a[1]), "r"(a[2]), "r"(a[3]), "r"(b[0]), "r"(b[1]));
}
#define CP_ASYNC16(dst, src) \
    asm volatile("cp.async.cg.shared.global [%0], [%1], 16;" :: "r"(dst), "l"(src) : "memory")
#define CP_COMMIT() asm volatile("cp.async.commit_group;" ::: "memory")
#define CP_WAIT0()  asm volatile("cp.async.wait_group 0;" ::: "memory")

// ---------------- weight conversion (single launch for all 4 matrices) --------
// W[k][n] row-major -> Wt[n][k] bf16 hi/lo, slots: Wv | Woff++Wattn | Wout
__global__ __launch_bounds__(256) void conv_wt_all(
    const float* __restrict__ Wv,   const float* __restrict__ Woff,
    const float* __restrict__ Wattn,const float* __restrict__ Wout,
    const float* __restrict__ boff, const float* __restrict__ battn,
    __nv_bfloat16* __restrict__ hi, __nv_bfloat16* __restrict__ lo,
    float* __restrict__ bqc)
{
    int idx = blockIdx.x * 256 + threadIdx.x;     // 896*256 total
    int ng = idx >> 8, k = idx & 255;
    float a;
    if (ng < 256)       a = Wv  [k * 256 + ng];
    else if (ng < 640) {
        int n = ng - 256;
        a = (n < 256) ? Woff[k * 256 + n] : Wattn[k * 128 + (n - 256)];
    } else              a = Wout[k * 256 + (ng - 640)];
    __nv_bfloat16 h = __float2bfloat16(a);
    hi[idx] = h;
    lo[idx] = __float2bfloat16(a - __bfloat162float(h));
    if (idx < 384) bqc[idx] = (idx < 256) ? boff[idx] : battn[idx - 256];
}

// ---------------- fused-convert HMMA GEMM ----------------
// C[M,N] = A_fp32[M,256] @ Wt^T + bias, split precision in-kernel:
//   C = Ahi*Bhi + Ahi*Blo + Alo*Bhi  (hi/lo built from fp32 A per K-chunk)
// Tile 128x128, BK=32, 8 chunks, 256 threads (8 warps, warp tile 32x64).
// Dynamic smem: 2 buffers x [Ahi|Alo|Bhi|Blo] of 128x(32+8pad) bf16 = 80KB.
constexpr int SBUF  = 40960;                       // one buffer: 4 x 10240B
constexpr int OF_AH = 0, OF_AL = 10240, OF_BH = 20480, OF_BL = 30720;
constexpr int GSMEM = 2 * SBUF;

__global__ __launch_bounds__(256, 2) void gemm_fused(
    const float* __restrict__ A,
    const __nv_bfloat16* __restrict__ Bhi, const __nv_bfloat16* __restrict__ Blo,
    const float* __restrict__ bias, float* __restrict__ C, int M, int ldc)
{
    extern __shared__ __align__(16) char smem[];
    const uint32_t sm0 = smem_u32(smem);

    const int tid = threadIdx.x, wid = tid >> 5, lane = tid & 31;
    const int m0 = blockIdx.x * 128, n0 = blockIdx.y * 128;
    const int wm = (wid & 3) * 32, wn = (wid >> 2) * 64;

    // A conversion coords: one row per thread-pair: row = tid>>1, k half = (tid&1)*16
    const int arow = tid >> 1, ak0 = (tid & 1) * 16;
    const bool avalid = (m0 + arow) < M;
    const float* aptr = A + (size_t)(m0 + arow) * 256 + ak0;

    // B cp.async coords: v = 2*tid + i: row = v>>2, 16B chunk c = v&3
    const int br = tid >> 1, bc2 = (tid & 1) * 2;  // two chunks bc2, bc2+1

    // ldmatrix lane addressing (byte offsets; row stride 80B)
    const uint32_t aRow = (lane & 15), aColB = (uint32_t)(lane >> 4) * 16;
    const uint32_t bRow = ((uint32_t)(lane >> 4) << 3) + (lane & 7);
    const uint32_t bColB = (uint32_t)((lane >> 3) & 1) * 16;

    float acc[2][8][4] = {};
    float fA[16];

    auto ldgA = [&](int ch) {
        if (avalid) {
            const float* p = aptr + ch * 32;
            #pragma unroll
            for (int j = 0; j < 4; ++j)
                *(float4*)&fA[j * 4] = *(const float4*)(p + j * 4);
        } else {
            #pragma unroll
            for (int j = 0; j < 16; ++j) fA[j] = 0.f;
        }
    };
    auto cvtStoreA = [&](uint32_t sb) {
        __nv_bfloat16 h[16], l[16];
        #pragma unroll
        for (int j = 0; j < 16; ++j) {
            h[j] = __float2bfloat16(fA[j]);
            l[j] = __float2bfloat16(fA[j] - __bfloat162float(h[j]));
        }
        const uint32_t o = arow * 80 + ak0 * 2;
        *(uint4*)(smem + (sb - sm0) + OF_AH + o)      = ((uint4*)h)[0];
        *(uint4*)(smem + (sb - sm0) + OF_AH + o + 16) = ((uint4*)h)[1];
        *(uint4*)(smem + (sb - sm0) + OF_AL + o)      = ((uint4*)l)[0];
        *(uint4*)(smem + (sb - sm0) + OF_AL + o + 16) = ((uint4*)l)[1];
    };
    auto ldB = [&](int ch, uint32_t sb) {
        const int k0 = ch * 32;
        #pragma unroll
        for (int i = 0; i < 2; ++i) {
            const int c = bc2 + i;
            const uint32_t dst = sb + br * 80 + c * 16;
            CP_ASYNC16(dst + OF_BH, Bhi + (size_t)(n0 + br) * 256 + k0 + c * 8);
            CP_ASYNC16(dst + OF_BL, Blo + (size_t)(n0 + br) * 256 + k0 + c * 8);
        }
        CP_COMMIT();
    };

    // prologue: stage chunk 0
    ldB(0, sm0);
    ldgA(0);
    cvtStoreA(sm0);
    CP_WAIT0();
    __syncthreads();

    for (int ch = 0; ch < 8; ++ch) {
        const uint32_t sb = sm0 + (ch & 1) * SBUF;
        const uint32_t nb = sm0 + ((ch + 1) & 1) * SBUF;
        if (ch < 7) { ldB(ch + 1, nb); ldgA(ch + 1); }

        #pragma unroll
        for (int ks = 0; ks < 2; ++ks) {
            const uint32_t kB = ks * 32;
            uint32_t afh[2][4], afl[2][4], bf[4][4];
            #pragma unroll
            for (int mt = 0; mt < 2; ++mt) {
                const uint32_t ao = (wm + mt * 16 + aRow) * 80 + kB + aColB;
                ldsm_x4(sb + OF_AH + ao, afh[mt]);
                ldsm_x4(sb + OF_AL + ao, afl[mt]);
            }
            #pragma unroll
            for (int p = 0; p < 4; ++p)
                ldsm_x4(sb + OF_BH + (wn + p * 16 + bRow) * 80 + kB + bColB, bf[p]);
            #pragma unroll
            for (int mt = 0; mt < 2; ++mt)
                #pragma unroll
                for (int nt = 0; nt < 8; ++nt) {
                    mma_bf16(acc[mt][nt], afh[mt], &bf[nt >> 1][(nt & 1) * 2]);
                    mma_bf16(acc[mt][nt], afl[mt], &bf[nt >> 1][(nt & 1) * 2]);
                }
            #pragma unroll
            for (int p = 0; p < 4; ++p)
                ldsm_x4(sb + OF_BL + (wn + p * 16 + bRow) * 80 + kB + bColB, bf[p]);
            #pragma unroll
            for (int mt = 0; mt < 2; ++mt)
                #pragma unroll
                for (int nt = 0; nt < 8; ++nt)
                    mma_bf16(acc[mt][nt], afh[mt], &bf[nt >> 1][(nt & 1) * 2]);
        }

        if (ch < 7) {
            cvtStoreA(nb);
            CP_WAIT0();
            __syncthreads();
        }
    }

    // epilogue: fragment (g=lane>>2, t=lane&3): c0,c1 -> (g, 2t); c2,c3 -> (g+8, 2t)
    const int g = lane >> 2, t2 = (lane & 3) * 2;
    #pragma unroll
    for (int mt = 0; mt < 2; ++mt) {
        const int r0 = m0 + wm + mt * 16 + g;
        #pragma unroll
        for (int nt = 0; nt < 8; ++nt) {
            const int c = n0 + wn + nt * 8 + t2;
            const float2 bsv = *(const float2*)(bias + c);
            if (r0 < M) {
                float2 o = { acc[mt][nt][0] + bsv.x, acc[mt][nt][1] + bsv.y };
                *(float2*)(C + (size_t)r0 * ldc + c) = o;
            }
            if (r0 + 8 < M) {
                float2 o = { acc[mt][nt][2] + bsv.x, acc[mt][nt][3] + bsv.y };
                *(float2*)(C + (size_t)(r0 + 8) * ldc + c) = o;
            }
        }
    }
}

// ---------------- deformable sampling: 4 queries/block, 4 heads/warp ----------------
__global__ __launch_bounds__(256) void sample_kernel(
    const float* __restrict__ refpts,   // [N*Lq, 4, 2]
    const float* __restrict__ value,    // [N*S, 256]
    const float* __restrict__ qc,       // [N*Lq, 384]: off(256) | logits(128)
    float* __restrict__ out)            // [N*Lq, 256]
{
    const int q0  = blockIdx.x * 4;
    const int tid = threadIdx.x;

    __shared__ float sh_w[4][8][17];
    __shared__ float sh_x[4][8][17];
    __shared__ float sh_y[4][8][17];

    // softmax weights: 32 runs of 16 logits, 16-lane segments
    #pragma unroll
    for (int i = 0; i < 2; ++i) {
        int run = i * 16 + (tid >> 4);
        int q = run >> 3, h = run & 7, l16 = tid & 15;
        float v = qc[(size_t)(q0 + q) * 384 + 256 + h * 16 + l16];
        float mx = v;
        #pragma unroll
        for (int o = 8; o > 0; o >>= 1) mx = fmaxf(mx, __shfl_xor_sync(0xffffffffu, mx, o));
        float e = __expf(v - mx);
        float s = e;
        #pragma unroll
        for (int o = 8; o > 0; o >>= 1) s += __shfl_xor_sync(0xffffffffu, s, o);
        sh_w[q][h][l16] = e / s;
    }

    // pixel coords: x = ref*W + off - 0.5
    #pragma unroll
    for (int q = 0; q < 4; ++q) {
        int h = tid >> 5, l32 = tid & 31;
        int lvl = l32 >> 3, cc = l32 & 1, s = l32 >> 1;
        float off = qc[(size_t)(q0 + q) * 384 + tid];
        float ref = refpts[((size_t)(q0 + q) * 4 + lvl) * 2 + cc];
        float pix = fmaf(ref, (float)c_WH[lvl], off) - 0.5f;
        if (cc == 0) sh_x[q][h][s] = pix; else sh_y[q][h][s] = pix;
    }
    __syncthreads();

    // gather: warp = (query, head-half); lane: 4 heads x 8 float4 channels
    const int w = tid >> 5, lane = tid & 31;
    const int q = w >> 1, half = w & 1;
    const int head = half * 4 + (lane >> 3);
    const int ci = lane & 7;
    const int qg = q0 + q;
    const int n  = (qg >= LQ) ? 1 : 0;

    const float4* v4 = (const float4*)value + (size_t)n * LQ * 64 + head * 8 + ci;
    float4 acc = make_float4(0.f, 0.f, 0.f, 0.f);

    const int WHl[4] = {100, 50, 25, 13};
    const int STl[4] = {0, 10000, 12500, 13125};

    #pragma unroll
    for (int s = 0; s < 16; ++s) {
        const int lvl = s >> 2;
        const int Wl = WHl[lvl], st = STl[lvl];
        float x = sh_x[q][head][s];
        float y = sh_y[q][head][s];
        float aw = sh_w[q][head][s];
        float xf = floorf(x), yf = floorf(y);
        int x0 = (int)xf, y0 = (int)yf;
        float wx = x - xf, wy = y - yf;
        #pragma unroll
        for (int dy = 0; dy < 2; ++dy) {
            int yi = y0 + dy;
            if (yi < 0 || yi >= Wl) continue;
            float wyy = dy ? wy : (1.f - wy);
            #pragma unroll
            for (int dx = 0; dx < 2; ++dx) {
                int xi = x0 + dx;
                if (xi < 0 || xi >= Wl) continue;
                float gw = aw * wyy * (dx ? wx : (1.f - wx));
                float4 v = __ldg(v4 + (st + yi * Wl + xi) * 64);
                acc.x = fmaf(gw, v.x, acc.x);
                acc.y = fmaf(gw, v.y, acc.y);
                acc.z = fmaf(gw, v.z, acc.z);
                acc.w = fmaf(gw, v.w, acc.w);
            }
        }
    }
    ((float4*)out)[(size_t)qg * 64 + head * 8 + ci] = acc;
}

// ---------------- launch ----------------
extern "C" void kernel_launch(void* const* d_in, const int* in_sizes, int n_in,
                              void* d_out, int out_size)
{
    const float* query  = (const float*)d_in[0];
    const float* refpts = (const float*)d_in[1];
    const float* flat   = (const float*)d_in[2];
    const float* Wv     = (const float*)d_in[5];
    const float* bv     = (const float*)d_in[6];
    const float* Woff   = (const float*)d_in[7];
    const float* boff   = (const float*)d_in[8];
    const float* Wattn  = (const float*)d_in[9];
    const float* battn  = (const float*)d_in[10];
    const float* Wout   = (const float*)d_in[11];
    const float* bout   = (const float*)d_in[12];
    float* out = (float*)d_out;

    float *gv, *gqc, *gs, *gbqc;
    __nv_bfloat16 *whi, *wlo;
    cudaGetSymbolAddress((void**)&gv,   g_value);
    cudaGetSymbolAddress((void**)&gqc,  g_qc);
    cudaGetSymbolAddress((void**)&gs,   g_samp);
    cudaGetSymbolAddress((void**)&gbqc, g_bqc);
    cudaGetSymbolAddress((void**)&whi,  g_wthi);
    cudaGetSymbolAddress((void**)&wlo,  g_wtlo);

    static bool attr_done = false;
    if (!attr_done) {
        cudaFuncSetAttribute(gemm_fused, cudaFuncAttributeMaxDynamicSharedMemorySize, GSMEM);
        attr_done = true;
    }

    __nv_bfloat16 *wv_h = whi + 0,          *wv_l = wlo + 0;
    __nv_bfloat16 *wq_h = whi + 256 * 256,  *wq_l = wlo + 256 * 256;
    __nv_bfloat16 *wu_h = whi + 640 * 256,  *wu_l = wlo + 640 * 256;

    conv_wt_all<<<896, 256>>>(Wv, Woff, Wattn, Wout, boff, battn, whi, wlo, gbqc);

    const int mblk = MPAD / 128;           // 208
    gemm_fused<<<dim3(mblk, 2), 256, GSMEM>>>(flat,  wv_h, wv_l, bv,   gv,  MROWS, 256);
    gemm_fused<<<dim3(mblk, 3), 256, GSMEM>>>(query, wq_h, wq_l, gbqc, gqc, MROWS, 384);
    sample_kernel<<<MROWS / 4, 256>>>(refpts, gv, gqc, gs);
    gemm_fused<<<dim3(mblk, 2), 256, GSMEM>>>(gs,    wu_h, wu_l, bout, out, MROWS, 256);
}

// round 5
// speedup vs baseline: 2.6501x; 1.0473x over previous
#include <cuda_runtime.h>
#include <cuda_bf16.h>
#include <cstdint>
#include <cstddef>

// ---------------- problem constants ----------------
constexpr int LQ    = 13294;
constexpr int MROWS = 2 * LQ;          // 26588
constexpr int MPAD  = 208 * 128;       // 26624

__constant__ int c_WH[4] = {100, 50, 25, 13};
__constant__ int c_ST[4] = {0, 10000, 12500, 13125};

// ---------------- scratch (device globals) ----------------
__device__ float g_value[MPAD * 256];
__device__ float g_qc   [MPAD * 384];             // [off(256) | logits(128)] per row
__device__ float g_samp [MPAD * 256];
__device__ float g_bqc  [384];                    // boff ++ battn
// transposed weights hi/lo: Wv [0,256), Wqc [256,640), Wout [640,896) rows of K=256
__device__ __nv_bfloat16 g_wthi[896 * 256];
__device__ __nv_bfloat16 g_wtlo[896 * 256];

// ---------------- PTX helpers (baseline sm_80+ ISA, legal on compute_103) ----
__device__ __forceinline__ uint32_t smem_u32(const void* p) {
    uint32_t a;
    asm("{ .reg .u64 t; cvta.to.shared.u64 t, %1; cvt.u32.u64 %0, t; }" : "=r"(a) : "l"(p));
    return a;
}
__device__ __forceinline__ void ldsm_x4(uint32_t addr, uint32_t* r) {
    asm volatile("ldmatrix.sync.aligned.m8n8.x4.shared.b16 {%0,%1,%2,%3}, [%4];"
                 : "=r"(r[0]), "=r"(r[1]), "=r"(r[2]), "=r"(r[3]) : "r"(addr));
}
__device__ __forceinline__ void mma_bf16(float* c, const uint32_t* a, const uint32_t* b) {
    asm volatile("mma.sync.aligned.m16n8k16.row.col.f32.bf16.bf16.f32 "
                 "{%0,%1,%2,%3}, {%4,%5,%6,%7}, {%8,%9}, {%0,%1,%2,%3};"
                 : "+f"(c[0]), "+f"(c[1]), "+f"(c[2]), "+f"(c[3])
                 : "r"(a[0]), "r"(a[1]), "r"(a[2]), "r"(a[3]), "r"(b[0]), "r"(b[1]));
}
#define CP_ASYNC16(dst, src) \
    asm volatile("cp.async.cg.shared.global [%0], [%1], 16;" :: "r"(dst), "l"(src) : "memory")
#define CP_COMMIT() asm volatile("cp.async.commit_group;" ::: "memory")
#define CP_WAIT0()  asm volatile("cp.async.wait_group 0;" ::: "memory")

// ---------------- weight conversion (one launch) ----------------
__global__ __launch_bounds__(256) void conv_wt_all(
    const float* __restrict__ Wv,   const float* __restrict__ Woff,
    const float* __restrict__ Wattn,const float* __restrict__ Wout,
    const float* __restrict__ boff, const float* __restrict__ battn,
    __nv_bfloat16* __restrict__ hi, __nv_bfloat16* __restrict__ lo,
    float* __restrict__ bqc)
{
    int idx = blockIdx.x * 256 + threadIdx.x;     // 896*256 total
    int ng = idx >> 8, k = idx & 255;
    float a;
    if (ng < 256)       a = Wv  [k * 256 + ng];
    else if (ng < 640) {
        int n = ng - 256;
        a = (n < 256) ? Woff[k * 256 + n] : Wattn[k * 128 + (n - 256)];
    } else              a = Wout[k * 256 + (ng - 640)];
    __nv_bfloat16 h = __float2bfloat16(a);
    hi[idx] = h;
    lo[idx] = __float2bfloat16(a - __bfloat162float(h));
    if (idx < 384) bqc[idx] = (idx < 256) ? boff[idx] : battn[idx - 256];
}

// ---------------- fused-convert HMMA GEMM core ----------------
// C[M,N] = A_fp32[M,256] @ Wt^T + bias, split: Ahi*Bhi + Ahi*Blo + Alo*Bhi.
// Tile 128x128, BK=32, 256 threads (8 warps, warp tile 32x64).
constexpr int SBUF  = 40960;                       // one buffer: 4 x 10240B
constexpr int OF_AH = 0, OF_AL = 10240, OF_BH = 20480, OF_BL = 30720;
constexpr int GSMEM = 2 * SBUF;

__device__ __forceinline__ void gemm_core(
    const float* __restrict__ A,
    const __nv_bfloat16* __restrict__ Bhi, const __nv_bfloat16* __restrict__ Blo,
    const float* __restrict__ bias, float* __restrict__ C,
    int M, int ldc, int m0, int n0, char* smem)
{
    const uint32_t sm0 = smem_u32(smem);
    const int tid = threadIdx.x, wid = tid >> 5, lane = tid & 31;
    const int wm = (wid & 3) * 32, wn = (wid >> 2) * 64;

    const int arow = tid >> 1, ak0 = (tid & 1) * 16;
    const bool avalid = (m0 + arow) < M;
    const float* aptr = A + (size_t)(m0 + arow) * 256 + ak0;

    const int br = tid >> 1, bc2 = (tid & 1) * 2;

    const uint32_t aRow = (lane & 15), aColB = (uint32_t)(lane >> 4) * 16;
    const uint32_t bRow = ((uint32_t)(lane >> 4) << 3) + (lane & 7);
    const uint32_t bColB = (uint32_t)((lane >> 3) & 1) * 16;

    float acc[2][8][4] = {};
    float fA[16];

    auto ldgA = [&](int ch) {
        if (avalid) {
            const float* p = aptr + ch * 32;
            #pragma unroll
            for (int j = 0; j < 4; ++j)
                *(float4*)&fA[j * 4] = *(const float4*)(p + j * 4);
        } else {
            #pragma unroll
            for (int j = 0; j < 16; ++j) fA[j] = 0.f;
        }
    };
    auto cvtStoreA = [&](uint32_t off) {
        __nv_bfloat16 h[16], l[16];
        #pragma unroll
        for (int j = 0; j < 16; ++j) {
            h[j] = __float2bfloat16(fA[j]);
            l[j] = __float2bfloat16(fA[j] - __bfloat162float(h[j]));
        }
        const uint32_t o = arow * 80 + ak0 * 2;
        *(uint4*)(smem + off + OF_AH + o)      = ((uint4*)h)[0];
        *(uint4*)(smem + off + OF_AH + o + 16) = ((uint4*)h)[1];
        *(uint4*)(smem + off + OF_AL + o)      = ((uint4*)l)[0];
        *(uint4*)(smem + off + OF_AL + o + 16) = ((uint4*)l)[1];
    };
    auto ldB = [&](int ch, uint32_t sb) {
        const int k0 = ch * 32;
        #pragma unroll
        for (int i = 0; i < 2; ++i) {
            const int c = bc2 + i;
            const uint32_t dst = sb + br * 80 + c * 16;
            CP_ASYNC16(dst + OF_BH, Bhi + (size_t)(n0 + br) * 256 + k0 + c * 8);
            CP_ASYNC16(dst + OF_BL, Blo + (size_t)(n0 + br) * 256 + k0 + c * 8);
        }
        CP_COMMIT();
    };

    ldB(0, sm0);
    ldgA(0);
    cvtStoreA(0);
    CP_WAIT0();
    __syncthreads();

    for (int ch = 0; ch < 8; ++ch) {
        const uint32_t sb = sm0 + (ch & 1) * SBUF;
        const uint32_t nbo = ((ch + 1) & 1) * SBUF;
        if (ch < 7) { ldB(ch + 1, sm0 + nbo); ldgA(ch + 1); }

        #pragma unroll
        for (int ks = 0; ks < 2; ++ks) {
            const uint32_t kB = ks * 32;
            uint32_t afh[2][4], afl[2][4], bf[4][4];
            #pragma unroll
            for (int mt = 0; mt < 2; ++mt) {
                const uint32_t ao = (wm + mt * 16 + aRow) * 80 + kB + aColB;
                ldsm_x4(sb + OF_AH + ao, afh[mt]);
                ldsm_x4(sb + OF_AL + ao, afl[mt]);
            }
            #pragma unroll
            for (int p = 0; p < 4; ++p)
                ldsm_x4(sb + OF_BH + (wn + p * 16 + bRow) * 80 + kB + bColB, bf[p]);
            #pragma unroll
            for (int mt = 0; mt < 2; ++mt)
                #pragma unroll
                for (int nt = 0; nt < 8; ++nt) {
                    mma_bf16(acc[mt][nt], afh[mt], &bf[nt >> 1][(nt & 1) * 2]);
                    mma_bf16(acc[mt][nt], afl[mt], &bf[nt >> 1][(nt & 1) * 2]);
                }
            #pragma unroll
            for (int p = 0; p < 4; ++p)
                ldsm_x4(sb + OF_BL + (wn + p * 16 + bRow) * 80 + kB + bColB, bf[p]);
            #pragma unroll
            for (int mt = 0; mt < 2; ++mt)
                #pragma unroll
                for (int nt = 0; nt < 8; ++nt)
                    mma_bf16(acc[mt][nt], afh[mt], &bf[nt >> 1][(nt & 1) * 2]);
        }

        if (ch < 7) {
            cvtStoreA(nbo);
            CP_WAIT0();
            __syncthreads();
        }
    }

    const int g = lane >> 2, t2 = (lane & 3) * 2;
    #pragma unroll
    for (int mt = 0; mt < 2; ++mt) {
        const int r0 = m0 + wm + mt * 16 + g;
        #pragma unroll
        for (int nt = 0; nt < 8; ++nt) {
            const int c = n0 + wn + nt * 8 + t2;
            const float2 bsv = *(const float2*)(bias + c);
            if (r0 < M) {
                float2 o = { acc[mt][nt][0] + bsv.x, acc[mt][nt][1] + bsv.y };
                *(float2*)(C + (size_t)r0 * ldc + c) = o;
            }
            if (r0 + 8 < M) {
                float2 o = { acc[mt][nt][2] + bsv.x, acc[mt][nt][3] + bsv.y };
                *(float2*)(C + (size_t)(r0 + 8) * ldc + c) = o;
            }
        }
    }
}

// merged value+qc GEMM: grid.y in [0,5): y<2 -> value (N=256), y>=2 -> qc (N=384)
__global__ __launch_bounds__(256, 2) void gemm_dual(
    const float* __restrict__ A0, const __nv_bfloat16* __restrict__ B0h,
    const __nv_bfloat16* __restrict__ B0l, const float* __restrict__ bias0,
    float* __restrict__ C0,
    const float* __restrict__ A1, const __nv_bfloat16* __restrict__ B1h,
    const __nv_bfloat16* __restrict__ B1l, const float* __restrict__ bias1,
    float* __restrict__ C1)
{
    extern __shared__ __align__(16) char smem[];
    const int m0 = blockIdx.x * 128;
    if (blockIdx.y < 2)
        gemm_core(A0, B0h, B0l, bias0, C0, MROWS, 256, m0, blockIdx.y * 128, smem);
    else
        gemm_core(A1, B1h, B1l, bias1, C1, MROWS, 384, m0, (blockIdx.y - 2) * 128, smem);
}

__global__ __launch_bounds__(256, 2) void gemm_single(
    const float* __restrict__ A, const __nv_bfloat16* __restrict__ Bhi,
    const __nv_bfloat16* __restrict__ Blo, const float* __restrict__ bias,
    float* __restrict__ C, int M, int ldc)
{
    extern __shared__ __align__(16) char smem[];
    gemm_core(A, Bhi, Blo, bias, C, M, ldc, blockIdx.x * 128, blockIdx.y * 128, smem);
}

// ---------------- deformable sampling v2: precomputed corner table ----------------
// Block = 4 queries, 256 threads. Phase A: softmax + coords. Phase B: 2048
// (weight, byte-offset) corner pairs computed once. Phase C: gather-only loop.
__global__ __launch_bounds__(256) void sample_kernel(
    const float* __restrict__ refpts,   // [N*Lq, 4, 2]
    const float* __restrict__ value,    // [N*S, 256]
    const float* __restrict__ qc,       // [N*Lq, 384]: off(256) | logits(128)
    float* __restrict__ out)            // [N*Lq, 256]
{
    const int q0  = blockIdx.x * 4;
    const int tid = threadIdx.x;

    __shared__ float sh_w[4][8][17];
    __shared__ float sh_x[4][8][17];
    __shared__ float sh_y[4][8][17];
    __shared__ __align__(16) float2 sh_p[4][8][64];   // (weight, byte-offset) per corner

    // phase A1: softmax weights (32 runs of 16 logits, 16-lane segments)
    #pragma unroll
    for (int i = 0; i < 2; ++i) {
        int run = i * 16 + (tid >> 4);
        int q = run >> 3, h = run & 7, l16 = tid & 15;
        float v = qc[(size_t)(q0 + q) * 384 + 256 + h * 16 + l16];
        float mx = v;
        #pragma unroll
        for (int o = 8; o > 0; o >>= 1) mx = fmaxf(mx, __shfl_xor_sync(0xffffffffu, mx, o));
        float e = __expf(v - mx);
        float s = e;
        #pragma unroll
        for (int o = 8; o > 0; o >>= 1) s += __shfl_xor_sync(0xffffffffu, s, o);
        sh_w[q][h][l16] = e / s;
    }

    // phase A2: pixel coords x = ref*W + off - 0.5
    #pragma unroll
    for (int q = 0; q < 4; ++q) {
        int h = tid >> 5, l32 = tid & 31;
        int lvl = l32 >> 3, cc = l32 & 1, s = l32 >> 1;
        float off = qc[(size_t)(q0 + q) * 384 + tid];
        float ref = refpts[((size_t)(q0 + q) * 4 + lvl) * 2 + cc];
        float pix = fmaf(ref, (float)c_WH[lvl], off) - 0.5f;
        if (cc == 0) sh_x[q][h][s] = pix; else sh_y[q][h][s] = pix;
    }
    __syncthreads();

    // phase B: 2048 corners, 8 per thread: (q,h,s,c) -> (gw, byteoff)
    #pragma unroll
    for (int i = 0; i < 8; ++i) {
        const int e = i * 256 + tid;
        const int q = e >> 9, h = (e >> 6) & 7, s = (e >> 2) & 15, c = e & 3;
        const int lvl = s >> 2;
        const int Wl = c_WH[lvl], st = c_ST[lvl];
        const float x = sh_x[q][h][s], y = sh_y[q][h][s], aw = sh_w[q][h][s];
        const float xf = floorf(x), yf = floorf(y);
        const float wx = x - xf, wy = y - yf;
        const int xi = (int)xf + (c & 1);
        const int yi = (int)yf + (c >> 1);
        const float gw = aw * ((c >> 1) ? wy : 1.f - wy) * ((c & 1) ? wx : 1.f - wx);
        const bool valid = (xi >= 0) & (xi < Wl) & (yi >= 0) & (yi < Wl);
        float2 pr;
        pr.x = valid ? gw : 0.f;
        pr.y = __int_as_float(valid ? (st + yi * Wl + xi) * 1024 : 0);
        sh_p[q][h][s * 4 + c] = pr;
    }
    __syncthreads();

    // phase C: gather. warp = (query, head-half); lane: 4 heads x 8 float4 channels
    const int w = tid >> 5, lane = tid & 31;
    const int q = w >> 1, half = w & 1;
    const int head = half * 4 + (lane >> 3);
    const int ci = lane & 7;
    const int qg = q0 + q;
    const int n  = (qg >= LQ) ? 1 : 0;

    const char* vb = (const char*)value + ((size_t)n * LQ * 64 + head * 8 + ci) * 16;
    const float4* pp = (const float4*)&sh_p[q][head][0];   // 32 float4 = 64 pairs
    float4 acc = make_float4(0.f, 0.f, 0.f, 0.f);

    #pragma unroll 8
    for (int i = 0; i < 32; ++i) {
        const float4 pw = pp[i];
        const float4 v0 = __ldg((const float4*)(vb + (uint32_t)__float_as_int(pw.y)));
        const float4 v1 = __ldg((const float4*)(vb + (uint32_t)__float_as_int(pw.w)));
        acc.x = fmaf(pw.x, v0.x, acc.x);
        acc.y = fmaf(pw.x, v0.y, acc.y);
        acc.z = fmaf(pw.x, v0.z, acc.z);
        acc.w = fmaf(pw.x, v0.w, acc.w);
        acc.x = fmaf(pw.z, v1.x, acc.x);
        acc.y = fmaf(pw.z, v1.y, acc.y);
        acc.z = fmaf(pw.z, v1.z, acc.z);
        acc.w = fmaf(pw.z, v1.w, acc.w);
    }
    ((float4*)out)[(size_t)qg * 64 + head * 8 + ci] = acc;
}

// ---------------- launch ----------------
extern "C" void kernel_launch(void* const* d_in, const int* in_sizes, int n_in,
                              void* d_out, int out_size)
{
    const float* query  = (const float*)d_in[0];
    const float* refpts = (const float*)d_in[1];
    const float* flat   = (const float*)d_in[2];
    const float* Wv     = (const float*)d_in[5];
    const float* bv     = (const float*)d_in[6];
    const float* Woff   = (const float*)d_in[7];
    const float* boff   = (const float*)d_in[8];
    const float* Wattn  = (const float*)d_in[9];
    const float* battn  = (const float*)d_in[10];
    const float* Wout   = (const float*)d_in[11];
    const float* bout   = (const float*)d_in[12];
    float* out = (float*)d_out;

    float *gv, *gqc, *gs, *gbqc;
    __nv_bfloat16 *whi, *wlo;
    cudaGetSymbolAddress((void**)&gv,   g_value);
    cudaGetSymbolAddress((void**)&gqc,  g_qc);
    cudaGetSymbolAddress((void**)&gs,   g_samp);
    cudaGetSymbolAddress((void**)&gbqc, g_bqc);
    cudaGetSymbolAddress((void**)&whi,  g_wthi);
    cudaGetSymbolAddress((void**)&wlo,  g_wtlo);

    static bool attr_done = false;
    if (!attr_done) {
        cudaFuncSetAttribute(gemm_dual,   cudaFuncAttributeMaxDynamicSharedMemorySize, GSMEM);
        cudaFuncSetAttribute(gemm_single, cudaFuncAttributeMaxDynamicSharedMemorySize, GSMEM);
        attr_done = true;
    }

    __nv_bfloat16 *wv_h = whi + 0,          *wv_l = wlo + 0;
    __nv_bfloat16 *wq_h = whi + 256 * 256,  *wq_l = wlo + 256 * 256;
    __nv_bfloat16 *wu_h = whi + 640 * 256,  *wu_l = wlo + 640 * 256;

    conv_wt_all<<<896, 256>>>(Wv, Woff, Wattn, Wout, boff, battn, whi, wlo, gbqc);

    const int mblk = MPAD / 128;           // 208
    gemm_dual<<<dim3(mblk, 5), 256, GSMEM>>>(flat, wv_h, wv_l, bv, gv,
                                             query, wq_h, wq_l, gbqc, gqc);
    sample_kernel<<<MROWS / 4, 256>>>(refpts, gv, gqc, gs);
    gemm_single<<<dim3(mblk, 2), 256, GSMEM>>>(gs, wu_h, wu_l, bout, out, MROWS, 256);
}